// round 2
// baseline (speedup 1.0000x reference)
#include <cuda_runtime.h>
#include <cstdint>
#include <math.h>

#define BATCH 256
#define SEQ   256
#define NIN   512
#define HD    1024
#define H4    4096
#define MOUT  512

// GEMM tiling
#define BM 64
#define BN 128
#define BK 32
#define SSTR 36           // padded smem row stride in floats (16B aligned, conflict-free)
#define ZS   132          // zbuf row stride

#define SMEM_BYTES ((2*BM*SSTR + 2*BN*SSTR) * 4)   // 55296

// ---------------------------------------------------------------------------
// Scratch (device globals)
// ---------------------------------------------------------------------------
__device__ float g_pre[(size_t)BATCH * SEQ * H4];   // [b][s][4H]
__device__ float g_h[2][BATCH * HD];                // ping-pong hidden (tf32-rounded)
__device__ float g_c[BATCH * HD];                   // cell state (fp32)
__device__ float g_xt[(size_t)BATCH * SEQ * NIN];   // tf32-rounded x
__device__ float g_whg[(size_t)H4 * HD];            // gathered Wh: row j*4+g
__device__ float g_wxc[(size_t)H4 * NIN];           // concat Wx (gate-major rows)
__device__ float g_wpt[(size_t)MOUT * HD];          // tf32-rounded Wp
__device__ float g_bxc[H4];                         // concat input bias

// ---------------------------------------------------------------------------
// Helpers
// ---------------------------------------------------------------------------
__device__ __forceinline__ float tf32f(float x) {
    uint32_t u;
    asm("cvt.rna.tf32.f32 %0, %1;" : "=r"(u) : "f"(x));
    return __uint_as_float(u);
}

__device__ __forceinline__ void mma_tf32(float d[4], const uint32_t a[4],
                                         const uint32_t b[2]) {
    asm volatile(
        "mma.sync.aligned.m16n8k8.row.col.f32.tf32.tf32.f32 "
        "{%0,%1,%2,%3}, {%4,%5,%6,%7}, {%8,%9}, {%0,%1,%2,%3};\n"
        : "+f"(d[0]), "+f"(d[1]), "+f"(d[2]), "+f"(d[3])
        : "r"(a[0]), "r"(a[1]), "r"(a[2]), "r"(a[3]), "r"(b[0]), "r"(b[1]));
}

__device__ __forceinline__ void cp16(uint32_t dst, const void* src) {
    asm volatile("cp.async.cg.shared.global [%0], [%1], 16;\n"
                 :: "r"(dst), "l"(src));
}
__device__ __forceinline__ void cp_commit() {
    asm volatile("cp.async.commit_group;\n");
}
template <int N>
__device__ __forceinline__ void cp_wait() {
    asm volatile("cp.async.wait_group %0;\n" :: "n"(N));
}

__device__ __forceinline__ float fsigm(float z) {
    return 1.0f / (1.0f + __expf(-z));
}
__device__ __forceinline__ float ftanh(float z) {
    // tanh(z) = 1 - 2/(e^{2z}+1); __expf handles inf/0 limits correctly.
    return 1.0f - 2.0f / (__expf(2.0f * z) + 1.0f);
}

// ---------------------------------------------------------------------------
// GEMM core: C = A @ B^T with cp.async double buffering.
// MODE 0: plain epilogue (C + bias).
// MODE 1: fused LSTM epilogue. B is gathered Wh (row = j*4+g). The block
//         computes z for all 4 gates over (64 batch x 32 j), stages z through
//         SMEM, then does the c/h pointwise update in place.
// ---------------------------------------------------------------------------
struct KParams {
    const float* A;       // [M, K] row-major (tf32-rounded values)
    const float* B;       // [Ntot, K] row-major (tf32-rounded values)
    float* C;             // [M, N] (mode 0)
    const float* bias;    // [Ntot] (mode 0, may be null)
    int K, N;
    int t;                // timestep (mode 1)
    float* c_state;       // (mode 1)
    float* h_out;         // (mode 1)
};

extern __shared__ float smem[];

template <int MODE>
__global__ __launch_bounds__(256, 2) void gemm2(KParams p) {
    const int tid  = threadIdx.x;
    const int lane = tid & 31;
    const int warp = tid >> 5;
    const int wm = warp >> 2, wn = warp & 3;
    const int lr = lane >> 2, lc = lane & 3;
    const int m0 = blockIdx.y * BM;
    const int n0 = blockIdx.x * BN;
    const int K = p.K;
    const int nk = K / BK;

    float* sA = smem;                       // 2 x 64 x SSTR
    float* sB = smem + 2 * BM * SSTR;       // 2 x 128 x SSTR

    auto issue = [&](int kt, int buf) {
        int k0 = kt * BK;
        float* bufA = sA + buf * BM * SSTR;
        float* bufB = sB + buf * BN * SSTR;
#pragma unroll
        for (int j = 0; j < 2; j++) {
            int i = tid + 256 * j;
            int r = i >> 3, c4 = i & 7;
            cp16((uint32_t)__cvta_generic_to_shared(bufA + r * SSTR + c4 * 4),
                 p.A + (size_t)(m0 + r) * K + k0 + c4 * 4);
        }
#pragma unroll
        for (int j = 0; j < 4; j++) {
            int i = tid + 256 * j;
            int r = i >> 3, c4 = i & 7;
            cp16((uint32_t)__cvta_generic_to_shared(bufB + r * SSTR + c4 * 4),
                 p.B + (size_t)(n0 + r) * K + k0 + c4 * 4);
        }
        cp_commit();
    };

    float acc[2][4][4];
#pragma unroll
    for (int mt = 0; mt < 2; mt++)
#pragma unroll
        for (int nt = 0; nt < 4; nt++)
#pragma unroll
            for (int e = 0; e < 4; e++) acc[mt][nt][e] = 0.0f;

    issue(0, 0);

    for (int kt = 0; kt < nk; kt++) {
        if (kt + 1 < nk) {
            issue(kt + 1, (kt + 1) & 1);
            cp_wait<1>();
        } else {
            cp_wait<0>();
        }
        __syncthreads();

        const float* bA = sA + (kt & 1) * BM * SSTR;
        const float* bB = sB + (kt & 1) * BN * SSTR;
#pragma unroll
        for (int kk = 0; kk < BK; kk += 8) {
            uint32_t a[2][4], b[4][2];
#pragma unroll
            for (int mt = 0; mt < 2; mt++) {
                int mb = wm * 32 + mt * 16;
                a[mt][0] = __float_as_uint(bA[(mb + lr) * SSTR + kk + lc]);
                a[mt][1] = __float_as_uint(bA[(mb + 8 + lr) * SSTR + kk + lc]);
                a[mt][2] = __float_as_uint(bA[(mb + lr) * SSTR + kk + 4 + lc]);
                a[mt][3] = __float_as_uint(bA[(mb + 8 + lr) * SSTR + kk + 4 + lc]);
            }
#pragma unroll
            for (int nt = 0; nt < 4; nt++) {
                int nb = wn * 32 + nt * 8;
                b[nt][0] = __float_as_uint(bB[(nb + lr) * SSTR + kk + lc]);
                b[nt][1] = __float_as_uint(bB[(nb + lr) * SSTR + kk + 4 + lc]);
            }
#pragma unroll
            for (int mt = 0; mt < 2; mt++)
#pragma unroll
                for (int nt = 0; nt < 4; nt++) mma_tf32(acc[mt][nt], a[mt], b[nt]);
        }
        __syncthreads();
    }

    if (MODE == 0) {
        const float* bp = p.bias;
        const int N = p.N;
#pragma unroll
        for (int mt = 0; mt < 2; mt++) {
#pragma unroll
            for (int nt = 0; nt < 4; nt++) {
                int r = m0 + wm * 32 + mt * 16 + lr;
                int cg = n0 + wn * 32 + nt * 8 + lc * 2;
                float bv0 = bp ? bp[cg] : 0.0f;
                float bv1 = bp ? bp[cg + 1] : 0.0f;
                float* C0 = p.C + (size_t)r * N;
                float* C1 = p.C + (size_t)(r + 8) * N;
                C0[cg]     = acc[mt][nt][0] + bv0;
                C0[cg + 1] = acc[mt][nt][1] + bv1;
                C1[cg]     = acc[mt][nt][2] + bv0;
                C1[cg + 1] = acc[mt][nt][3] + bv1;
            }
        }
    } else {
        // Stage z into smem (reuse GEMM buffers; mainloop ended with sync).
        float* zbuf = smem;  // 64 x ZS
#pragma unroll
        for (int mt = 0; mt < 2; mt++) {
#pragma unroll
            for (int nt = 0; nt < 4; nt++) {
                int rl = wm * 32 + mt * 16 + lr;
                int cl = wn * 32 + nt * 8 + lc * 2;
                zbuf[rl * ZS + cl]           = acc[mt][nt][0];
                zbuf[rl * ZS + cl + 1]       = acc[mt][nt][1];
                zbuf[(rl + 8) * ZS + cl]     = acc[mt][nt][2];
                zbuf[(rl + 8) * ZS + cl + 1] = acc[mt][nt][3];
            }
        }
        __syncthreads();

        const int j0 = n0 >> 2;  // gathered rows: global row = j*4 + gate
#pragma unroll
        for (int e = tid; e < BM * 32; e += 256) {
            int j  = e & 31;
            int bl = e >> 5;
            int bg = m0 + bl;
            int jg = j0 + j;
            const float* pp = g_pre + ((size_t)bg * SEQ + p.t) * H4 + jg;
            float zg = zbuf[bl * ZS + j * 4 + 0] + pp[0];
            float zi = zbuf[bl * ZS + j * 4 + 1] + pp[HD];
            float zf = zbuf[bl * ZS + j * 4 + 2] + pp[2 * HD];
            float zo = zbuf[bl * ZS + j * 4 + 3] + pp[3 * HD];
            float gg = ftanh(zg);
            float ii = fsigm(zi);
            float ff = fsigm(zf);
            float oo = fsigm(zo);
            size_t ci = (size_t)bg * HD + jg;
            float cn = gg * ii + p.c_state[ci] * ff;
            p.c_state[ci] = cn;
            p.h_out[ci] = tf32f(ftanh(cn) * oo);
        }
    }
}

// ---------------------------------------------------------------------------
// Conversion / setup kernels
// ---------------------------------------------------------------------------
__global__ void conv4_kernel(float4* dst, const float4* src, int n4) {
    int i = blockIdx.x * blockDim.x + threadIdx.x;
    if (i < n4) {
        float4 v = src[i];
        v.x = tf32f(v.x); v.y = tf32f(v.y); v.z = tf32f(v.z); v.w = tf32f(v.w);
        dst[i] = v;
    }
}

// Gather Wh_g into g_whg rows j*4+gate
__global__ void conv_wh_kernel(float* dst, const float* W, int gate) {
    int i = blockIdx.x * blockDim.x + threadIdx.x;  // over HD*HD
    if (i < HD * HD) {
        int j = i >> 10, k = i & (HD - 1);
        dst[((size_t)(j * 4 + gate)) * HD + k] = tf32f(W[i]);
    }
}

__global__ void bias_cat_kernel(float* dst, const float* b0, const float* b1,
                                const float* b2, const float* b3) {
    int i = blockIdx.x * blockDim.x + threadIdx.x;
    if (i < HD) {
        dst[i] = b0[i];
        dst[i + HD] = b1[i];
        dst[i + 2 * HD] = b2[i];
        dst[i + 3 * HD] = b3[i];
    }
}

__global__ void zero_state_kernel() {
    int idx = blockIdx.x * blockDim.x + threadIdx.x;
    if (idx < BATCH * HD) {
        g_h[0][idx] = 0.0f;
        g_c[idx] = 0.0f;
    }
}

// ---------------------------------------------------------------------------
// Driver
// ---------------------------------------------------------------------------
extern "C" void kernel_launch(void* const* d_in, const int* in_sizes, int n_in,
                              void* d_out, int out_size) {
    const float* x    = (const float*)d_in[0];
    const float* Wgx  = (const float*)d_in[1];
    const float* bgx  = (const float*)d_in[2];
    const float* Wgh  = (const float*)d_in[3];
    const float* Wix  = (const float*)d_in[4];
    const float* bix  = (const float*)d_in[5];
    const float* Wih  = (const float*)d_in[6];
    const float* Wfx  = (const float*)d_in[7];
    const float* bfx  = (const float*)d_in[8];
    const float* Wfh  = (const float*)d_in[9];
    const float* Wox  = (const float*)d_in[10];
    const float* box_ = (const float*)d_in[11];
    const float* Woh  = (const float*)d_in[12];
    const float* Wp   = (const float*)d_in[13];
    const float* bpb  = (const float*)d_in[14];
    float* out = (float*)d_out;

    float *pre_p, *h_p, *c_p, *xt_p, *whg_p, *wxc_p, *wpt_p, *bxc_p;
    cudaGetSymbolAddress((void**)&pre_p, g_pre);
    cudaGetSymbolAddress((void**)&h_p, g_h);
    cudaGetSymbolAddress((void**)&c_p, g_c);
    cudaGetSymbolAddress((void**)&xt_p, g_xt);
    cudaGetSymbolAddress((void**)&whg_p, g_whg);
    cudaGetSymbolAddress((void**)&wxc_p, g_wxc);
    cudaGetSymbolAddress((void**)&wpt_p, g_wpt);
    cudaGetSymbolAddress((void**)&bxc_p, g_bxc);

    cudaFuncSetAttribute(gemm2<0>, cudaFuncAttributeMaxDynamicSharedMemorySize,
                         SMEM_BYTES);
    cudaFuncSetAttribute(gemm2<1>, cudaFuncAttributeMaxDynamicSharedMemorySize,
                         SMEM_BYTES);

    // --- setup: tf32-round operands, gather layouts, zero state ---
    {
        int n4 = BATCH * SEQ * NIN / 4;
        conv4_kernel<<<(n4 + 255) / 256, 256>>>((float4*)xt_p, (const float4*)x, n4);
    }
    const float* wxs[4] = {Wgx, Wix, Wfx, Wox};
    for (int g = 0; g < 4; g++) {
        int n4 = HD * NIN / 4;
        conv4_kernel<<<(n4 + 255) / 256, 256>>>(
            (float4*)(wxc_p + (size_t)g * HD * NIN), (const float4*)wxs[g], n4);
    }
    const float* whs[4] = {Wgh, Wih, Wfh, Woh};
    for (int g = 0; g < 4; g++)
        conv_wh_kernel<<<(HD * HD + 255) / 256, 256>>>(whg_p, whs[g], g);
    {
        int n4 = MOUT * HD / 4;
        conv4_kernel<<<(n4 + 255) / 256, 256>>>((float4*)wpt_p, (const float4*)Wp, n4);
    }
    bias_cat_kernel<<<(HD + 255) / 256, 256>>>(bxc_p, bgx, bix, bfx, box_);
    zero_state_kernel<<<(BATCH * HD + 255) / 256, 256>>>();

    // --- input projection: pre = x @ Wx_cat^T + bx_cat ---
    {
        KParams a = {};
        a.A = xt_p; a.B = wxc_p; a.C = pre_p; a.bias = bxc_p;
        a.K = NIN; a.N = H4;
        gemm2<0><<<dim3(H4 / BN, (BATCH * SEQ) / BM), 256, SMEM_BYTES>>>(a);
    }

    // --- recurrence: fused z = h @ Whg^T + gate update ---
    for (int t = 0; t < SEQ; t++) {
        KParams a = {};
        a.A = h_p + (size_t)(t & 1) * (BATCH * HD);
        a.B = whg_p;
        a.K = HD; a.N = H4;
        a.t = t;
        a.c_state = c_p;
        a.h_out = h_p + (size_t)((t + 1) & 1) * (BATCH * HD);
        gemm2<1><<<dim3(H4 / BN, BATCH / BM), 256, SMEM_BYTES>>>(a);
    }

    // --- final projection: out = h_final @ Wp^T + bp (h_final in buffer 0) ---
    {
        KParams a = {};
        a.A = h_p; a.B = wpt_p; a.C = out; a.bias = bpb;
        a.K = HD; a.N = MOUT;
        gemm2<0><<<dim3(MOUT / BN, BATCH / BM), 256, SMEM_BYTES>>>(a);
    }
}